// round 8
// baseline (speedup 1.0000x reference)
#include <cuda_runtime.h>
#include <cuda_bf16.h>
#include <cstdint>
#include <math.h>

// ---------------- problem constants ----------------
constexpr int Bn = 1024, Hn = 256, Gn = 768, On = 512, Tn = 60, Cn = 15;
constexpr int NCTA = 120;               // 15 clusters x 8 CTAs
constexpr int VR = 1792;                // virtual weight rows per camera
constexpr int VR_CTA = 224;             // rows per CTA

// ---------------- device scratch (static, allocation-free) ----------------
__device__ __align__(1024) __nv_bfloat16 g_W [ (size_t)Cn * 1280 * 512 ]; // rows 0-767 W_hh, 768-1279 Wc; [row][hi256|lo256]
__device__ __align__(1024) __nv_bfloat16 g_Wi[ (size_t)Cn * 768 * 512 ];  // W_ih split (for one-time gi GEMM)
__device__ __align__(1024) __nv_bfloat16 g_A [ (size_t)Cn * 128 * 512 ];  // A(h): [slot][hi|lo]
__device__ __align__(1024) __nv_bfloat16 g_Ax[ (size_t)Cn * 128 * 512 ];  // A(x)
__device__ float g_gi[Bn * Gn];
__device__ float g_gh[Bn * Gn];          // rz + n(hi*Whi) partial, biases folded
__device__ float g_pb[Bn * Hn];          // n partial: Alo * Whi_n
__device__ float g_pc[Bn * Hn];          // n partial: Ahi * Wlo_n
__device__ float g_h [Bn * Hn];
__device__ float g_outT[(size_t)Tn * Bn * On];   // [T][B][O] staging
__device__ int g_cnt[Cn], g_off[Cn], g_list[Bn], g_slot[Bn];

// ---------------- PTX helpers (family-agnostic) ----------------
__device__ __forceinline__ uint32_t smem_u32(const void* p) {
    uint32_t a;
    asm("{ .reg .u64 t; cvta.to.shared.u64 t, %1; cvt.u32.u64 %0, t; }" : "=r"(a) : "l"(p));
    return a;
}
__device__ __forceinline__ void ldsm4(uint32_t& r0, uint32_t& r1, uint32_t& r2, uint32_t& r3,
                                      uint32_t addr) {
    asm volatile("ldmatrix.sync.aligned.m8n8.x4.shared.b16 {%0,%1,%2,%3}, [%4];"
                 : "=r"(r0), "=r"(r1), "=r"(r2), "=r"(r3) : "r"(addr));
}
__device__ __forceinline__ void mma16816(float* d, const uint32_t* a, const uint32_t* b) {
    asm volatile("mma.sync.aligned.m16n8k16.row.col.f32.bf16.bf16.f32 "
                 "{%0,%1,%2,%3}, {%4,%5,%6,%7}, {%8,%9}, {%0,%1,%2,%3};"
                 : "+f"(d[0]), "+f"(d[1]), "+f"(d[2]), "+f"(d[3])
                 : "r"(a[0]), "r"(a[1]), "r"(a[2]), "r"(a[3]), "r"(b[0]), "r"(b[1]));
}
__device__ __forceinline__ void cp_async16(uint32_t dst, const void* src) {
    asm volatile("cp.async.cg.shared.global [%0], [%1], 16;" :: "r"(dst), "l"(src));
}
#define CP_COMMIT() asm volatile("cp.async.commit_group;" ::: "memory")
#define CP_WAIT1()  asm volatile("cp.async.wait_group 1;" ::: "memory")
#define CP_WAIT0()  asm volatile("cp.async.wait_group 0;" ::: "memory")
#define CLUSTER_ARRIVE() asm volatile("barrier.cluster.arrive.aligned;" ::: "memory")
#define CLUSTER_WAIT()   asm volatile("barrier.cluster.wait.aligned;" ::: "memory")

__device__ __forceinline__ uint32_t swz(uint32_t x) { return x ^ ((x >> 3) & 0x70); }
__device__ __forceinline__ float sigmoidf(float x) { return 1.0f / (1.0f + expf(-x)); }
__device__ __forceinline__ uint32_t pack_bf2(float a, float b) {
    __nv_bfloat162 t = {__float2bfloat16(a), __float2bfloat16(b)};
    return *(uint32_t*)&t;
}

// ---------------- grouping ----------------
__global__ void group_kernel(const int* __restrict__ cam) {
    __shared__ int cnt[Cn], off[Cn], cur[Cn];
    int tid = threadIdx.x;
    if (tid < Cn) { cnt[tid] = 0; cur[tid] = 0; }
    __syncthreads();
    int c = cam[tid];
    atomicAdd(&cnt[c], 1);
    __syncthreads();
    if (tid == 0) { int s = 0; for (int i = 0; i < Cn; i++) { off[i] = s; s += cnt[i]; } }
    __syncthreads();
    if (tid < Cn) { g_cnt[tid] = cnt[tid]; g_off[tid] = off[tid]; }
    int p = atomicAdd(&cur[c], 1);
    g_list[off[c] + p] = tid;
    g_slot[tid] = p;
}

// ---------------- weight hi/lo split ----------------
__global__ void prep_w_kernel(const float* __restrict__ W_hh, const float* __restrict__ Wc,
                              const float* __restrict__ W_ih) {
    int row = blockIdx.x & 2047;
    int c   = blockIdx.x >> 11;
    const float* src;
    __nv_bfloat16* dst;
    if (row < 768) {
        src = W_hh + ((size_t)c * Gn + row) * Hn;
        dst = g_W + ((size_t)c * 1280 + row) * 512;
    } else if (row < 1280) {
        src = Wc + ((size_t)c * On + (row - 768)) * Hn;
        dst = g_W + ((size_t)c * 1280 + row) * 512;
    } else {
        src = W_ih + ((size_t)c * Gn + (row - 1280)) * Hn;
        dst = g_Wi + ((size_t)c * 768 + (row - 1280)) * 512;
    }
    int k0 = threadIdx.x * 2;
    float2 v = *(const float2*)(src + k0);
    float h0 = __bfloat162float(__float2bfloat16(v.x));
    float h1 = __bfloat162float(__float2bfloat16(v.y));
    *(uint32_t*)(dst + k0)       = pack_bf2(v.x, v.y);
    *(uint32_t*)(dst + 256 + k0) = pack_bf2(v.x - h0, v.y - h1);
}

// ---------------- activation hi/lo split ----------------
__device__ __forceinline__ void write_A2(__nv_bfloat16* Abase, int c, int slot,
                                         int k0, float v0, float v1) {
    __nv_bfloat16* row = Abase + ((size_t)c * 128 + slot) * 512;
    float h0 = __bfloat162float(__float2bfloat16(v0));
    float h1 = __bfloat162float(__float2bfloat16(v1));
    *(uint32_t*)(row + k0)       = pack_bf2(v0, v1);
    *(uint32_t*)(row + 256 + k0) = pack_bf2(v0 - h0, v1 - h1);
}

__global__ void build_ax_kernel(const float* __restrict__ x, const int* __restrict__ cam) {
    int b = blockIdx.x, j0 = threadIdx.x * 2;
    float2 v = *(const float2*)(x + (size_t)b * Hn + j0);
    write_A2(g_Ax, cam[b], g_slot[b], j0, v.x, v.y);
}

// h0 = 0; gh0 = b_hh (bias folded); n-partials = 0
__global__ void init_kernel(const int* __restrict__ cam, const float* __restrict__ b_hh) {
    int b = blockIdx.x, j = threadIdx.x;
    int c = cam[b];
    g_h[b * Hn + j] = 0.0f;
    g_pb[b * Hn + j] = 0.0f;
    g_pc[b * Hn + j] = 0.0f;
    g_gh[b * Gn + j]       = b_hh[c * Gn + j];
    g_gh[b * Gn + 256 + j] = b_hh[c * Gn + 256 + j];
    g_gh[b * Gn + 512 + j] = b_hh[c * Gn + 512 + j];
}

// ---------------- gi GEMM (once): gi = x @ W_ih^T + b_ih (full 3-term) ----------------
__device__ __forceinline__ int aoff_f(int cc) { return (((cc >> 2) == 1) ? 256 : 0) + (cc & 3) * 64; }
__device__ __forceinline__ int boff_f(int cc) { return (((cc >> 2) == 2) ? 256 : 0) + (cc & 3) * 64; }

__device__ __forceinline__ void load_tile128(uint32_t sbase, const __nv_bfloat16* src,
                                             int koff, int tid) {
#pragma unroll
    for (int i = 0; i < 8; i++) {
        int idx = i * 128 + tid;
        int row = idx >> 3, c16 = idx & 7;
        cp_async16(sbase + swz((uint32_t)(row * 128 + c16 * 16)),
                   src + (size_t)row * 512 + koff + c16 * 8);
    }
}

constexpr int SMEM_GI = 65536 + 512;

__global__ void __launch_bounds__(128)
gi_kernel(const float* __restrict__ b_ih) {
    extern __shared__ __align__(1024) unsigned char smem[];
    uint32_t sb = smem_u32(smem);
    int tid = threadIdx.x;
    int ci = blockIdx.x / 6, nt = blockIdx.x % 6;
    int* Slist = (int*)(smem + 65536);
    Slist[tid] = (tid < g_cnt[ci]) ? g_list[g_off[ci] + tid] : -1;

    const __nv_bfloat16* Abase = g_Ax + (size_t)ci * 128 * 512;
    const __nv_bfloat16* Wbase = g_Wi + ((size_t)ci * 768 + nt * 128) * 512;

    load_tile128(sb, Abase, aoff_f(0), tid);
    load_tile128(sb + 16384, Wbase, boff_f(0), tid);
    CP_COMMIT();

    int lane = tid & 31, wid = tid >> 5;
    int warpM = wid & 1, warpN = wid >> 1;
    int arow = lane & 15, khalf = (lane >> 4) << 3;

    float acc[4][8][4];
#pragma unroll
    for (int mb = 0; mb < 4; mb++)
#pragma unroll
        for (int nb = 0; nb < 8; nb++)
#pragma unroll
            for (int q = 0; q < 4; q++) acc[mb][nb][q] = 0.0f;

    for (int cc = 0; cc < 12; cc++) {
        int st = cc & 1;
        if (cc < 11) {
            int s1 = st ^ 1;
            load_tile128(sb + s1 * 32768, Abase, aoff_f(cc + 1), tid);
            load_tile128(sb + s1 * 32768 + 16384, Wbase, boff_f(cc + 1), tid);
            CP_COMMIT();
            CP_WAIT1();
        } else CP_WAIT0();
        __syncthreads();
        uint32_t As = sb + st * 32768, Bs = As + 16384;
#pragma unroll
        for (int kc = 0; kc < 4; kc++) {
            int kb = (kc << 4) + khalf;
            uint32_t a[4][4];
#pragma unroll
            for (int mb = 0; mb < 4; mb++)
                ldsm4(a[mb][0], a[mb][1], a[mb][2], a[mb][3],
                      As + swz((uint32_t)((((warpM << 6) + (mb << 4) + arow) << 7) + (kb << 1))));
            uint32_t bq[8][2];
#pragma unroll
            for (int np = 0; np < 4; np++) {
                uint32_t r0, r1, r2, r3;
                ldsm4(r0, r1, r2, r3,
                      Bs + swz((uint32_t)((((warpN << 6) + (np << 4) + arow) << 7) + (kb << 1))));
                bq[np * 2][0] = r0; bq[np * 2 + 1][0] = r1;
                bq[np * 2][1] = r2; bq[np * 2 + 1][1] = r3;
            }
#pragma unroll
            for (int mb = 0; mb < 4; mb++)
#pragma unroll
                for (int nb = 0; nb < 8; nb++)
                    mma16816(acc[mb][nb], a[mb], bq[nb]);
        }
        __syncthreads();
    }

    int g = lane >> 2, tg = lane & 3;
#pragma unroll
    for (int mb = 0; mb < 4; mb++) {
        int m0 = (warpM << 6) + (mb << 4) + g;
        int b0 = Slist[m0], b1 = Slist[m0 + 8];
#pragma unroll
        for (int nb = 0; nb < 8; nb++) {
            float* d = acc[mb][nb];
            int n = nt * 128 + (warpN << 6) + (nb << 3) + (tg << 1);
            float2 bb = *(const float2*)(b_ih + (size_t)ci * Gn + n);
            if (b0 >= 0) *(float2*)(g_gi + (size_t)b0 * Gn + n) = make_float2(d[0] + bb.x, d[1] + bb.y);
            if (b1 >= 0) *(float2*)(g_gi + (size_t)b1 * Gn + n) = make_float2(d[2] + bb.x, d[3] + bb.y);
        }
    }
}

// ---------------- persistent clustered recurrence kernel ----------------
// Virtual 1792-row x K=256 GEMM per camera, balanced 8 CTAs x 224 rows:
//   v 0-511   : rz  (Ahi x Whi_rz)   -> g_gh[+b_hh]
//   v 512-767 : n   (Ahi x Whi_n)    -> g_gh[+b_hh]
//   v 768-1023: n   (Ahi x Wlo_n)    -> g_pc
//   v 1024-1535: out (Ahi x Wc_hi)   -> sigmoid(+bc) -> g_outT
//   v 1536-1791: n  (Alo x Whi_n)    -> g_pb
constexpr uint32_t WSUB = 29696;     // 232 rows x 128B (224 used, 8 pad)
constexpr uint32_t SB_W  = 0;        // 4 k-chunks x WSUB = 118784
constexpr uint32_t SB_A  = 118784;   // 2 stages x (16K hi + 16K lo) = 65536
constexpr uint32_t SB_SL = 184320;   // 128 ints
constexpr int SMEM_P = 184832 + 512;

__device__ __forceinline__ void load_A_hi(uint32_t dsthi, const __nv_bfloat16* Abase,
                                          int c, int tid) {
#pragma unroll
    for (int i = 0; i < 4; i++) {
        int idx = i * 256 + tid;
        int row = idx >> 3, c16 = idx & 7;
        cp_async16(dsthi + swz((uint32_t)(row * 128 + c16 * 16)),
                   Abase + (size_t)row * 512 + c * 64 + c16 * 8);
    }
}
__device__ __forceinline__ void load_A_lo(uint32_t dstlo, const __nv_bfloat16* Abase,
                                          int c, int tid) {
#pragma unroll
    for (int i = 0; i < 4; i++) {
        int idx = i * 256 + tid;
        int row = idx >> 3, c16 = idx & 7;
        cp_async16(dstlo + swz((uint32_t)(row * 128 + c16 * 16)),
                   Abase + (size_t)row * 512 + 256 + c * 64 + c16 * 8);
    }
}

__global__ void __cluster_dims__(8, 1, 1) __launch_bounds__(256, 1)
persist_kernel(const float* __restrict__ b_hh, const float* __restrict__ bc) {
    extern __shared__ __align__(1024) unsigned char smem[];
    uint32_t sb = smem_u32(smem);
    int tid = threadIdx.x, lane = tid & 31, wid = tid >> 5;
    int ci = blockIdx.x >> 3, rank = blockIdx.x & 7;
    bool needLo = (rank >= 6);            // only CTAs 6,7 touch v>=1536
    int* Slist = (int*)(smem + SB_SL);
    int cnt = g_cnt[ci];
    if (tid < 128) Slist[tid] = (tid < cnt) ? g_list[g_off[ci] + tid] : -1;

    // ---- prologue: resident virtual-weight tile (224 rows x 256 cols) ----
    for (int i = tid; i < 7168; i += 256) {        // 224*4*8 vec16
        int chunk = i / 1792, rem = i % 1792;
        int r = rem >> 3, c16 = rem & 7;
        int v = rank * VR_CTA + r;
        int srow, chalf;
        if (v < 768)       { srow = v;        chalf = 0; }
        else if (v < 1024) { srow = v - 256;  chalf = 1; }   // Wlo_n
        else if (v < 1536) { srow = v - 256;  chalf = 0; }   // Wc hi
        else               { srow = v - 1024; chalf = 0; }   // Whi_n (Alo partner)
        cp_async16(sb + SB_W + chunk * WSUB + swz((uint32_t)(r * 128 + c16 * 16)),
                   g_W + ((size_t)ci * 1280 + srow) * 512 + chalf * 256 + chunk * 64 + c16 * 8);
    }
    CP_COMMIT(); CP_WAIT0();
    __syncthreads();

    const __nv_bfloat16* Abase = g_A + (size_t)ci * 128 * 512;
    int warpN = wid & 3, warpM = wid >> 2;       // warpN = SMSP id
    int arow = lane & 15, khalf = (lane >> 4) << 3;
    int g = lane >> 2, tg = lane & 3;
    int gslot = rank * 16 + (tid >> 4), gj0 = (tid & 15) * 2;
    int vwarp = rank * VR_CTA + warpN * 56;
    bool loA[7];
#pragma unroll
    for (int nb = 0; nb < 7; nb++) loA[nb] = (vwarp + nb * 8) >= 1536;

    for (int t = 1; t <= Tn; t++) {
        // ---- GRU phase (16 slots per CTA) ----
        {
            int b = Slist[gslot];
            if (b >= 0) {
                const float* gi = g_gi + (size_t)b * Gn;
                const float* gh = g_gh + (size_t)b * Gn;
                float* hp = g_h + (size_t)b * Hn;
#pragma unroll
                for (int jj = 0; jj < 8; jj++) {
                    int j = gj0 + jj * 32;
                    float2 gr = __ldcg((const float2*)(gh + j));
                    float2 gz = __ldcg((const float2*)(gh + 256 + j));
                    float2 gn = __ldcg((const float2*)(gh + 512 + j));
                    float2 pb = __ldcg((const float2*)(g_pb + (size_t)b * Hn + j));
                    float2 pc = __ldcg((const float2*)(g_pc + (size_t)b * Hn + j));
                    float2 ir = *(const float2*)(gi + j);
                    float2 iz = *(const float2*)(gi + 256 + j);
                    float2 in_ = *(const float2*)(gi + 512 + j);
                    float2 h = *(const float2*)(hp + j);
                    float gnx = gn.x + pb.x + pc.x, gny = gn.y + pb.y + pc.y;
                    float r0 = sigmoidf(ir.x + gr.x), r1 = sigmoidf(ir.y + gr.y);
                    float z0 = sigmoidf(iz.x + gz.x), z1 = sigmoidf(iz.y + gz.y);
                    float n0 = tanhf(in_.x + r0 * gnx), n1 = tanhf(in_.y + r1 * gny);
                    float h0 = (1.0f - z0) * n0 + z0 * h.x;
                    float h1 = (1.0f - z1) * n1 + z1 * h.y;
                    *(float2*)(hp + j) = make_float2(h0, h1);
                    write_A2(g_A, ci, gslot, j, h0, h1);
                }
            }
        }
        CLUSTER_ARRIVE(); CLUSTER_WAIT();    // A(h_t) visible in-cluster

        // ---- unified MMA: 224 rows, K=256 ----
        float acc[4][7][4];
#pragma unroll
        for (int mb = 0; mb < 4; mb++)
#pragma unroll
            for (int nb = 0; nb < 7; nb++)
#pragma unroll
                for (int q = 0; q < 4; q++) acc[mb][nb][q] = 0.0f;

        load_A_hi(sb + SB_A, Abase, 0, tid);
        if (needLo) load_A_lo(sb + SB_A + 16384, Abase, 0, tid);
        CP_COMMIT();
        for (int c = 0; c < 4; c++) {
            int st = c & 1;
            if (c < 3) {
                uint32_t stg = sb + SB_A + (st ^ 1) * 32768;
                load_A_hi(stg, Abase, c + 1, tid);
                if (needLo) load_A_lo(stg + 16384, Abase, c + 1, tid);
                CP_COMMIT(); CP_WAIT1();
            } else CP_WAIT0();
            __syncthreads();
            uint32_t Ahi = sb + SB_A + st * 32768, Alo = Ahi + 16384;
            uint32_t Ws = sb + SB_W + c * WSUB;
#pragma unroll
            for (int kc = 0; kc < 4; kc++) {
                int kb = (kc << 4) + khalf;
                uint32_t ah[4][4], al[4][4];
#pragma unroll
                for (int mb = 0; mb < 4; mb++) {
                    int r0 = warpM * 64 + mb * 16;
                    if (r0 < cnt) {
                        uint32_t ro = (uint32_t)(((r0 + arow) << 7) + (kb << 1));
                        ldsm4(ah[mb][0], ah[mb][1], ah[mb][2], ah[mb][3], Ahi + swz(ro));
                        if (needLo)
                            ldsm4(al[mb][0], al[mb][1], al[mb][2], al[mb][3], Alo + swz(ro));
                    }
                }
                uint32_t bq[8][2];
#pragma unroll
                for (int np = 0; np < 4; np++) {
                    uint32_t ro = (uint32_t)(((warpN * 56 + np * 16 + arow) << 7) + (kb << 1));
                    uint32_t r0, r1, r2, r3;
                    ldsm4(r0, r1, r2, r3, Ws + swz(ro));
                    bq[np * 2][0] = r0; bq[np * 2 + 1][0] = r1;
                    bq[np * 2][1] = r2; bq[np * 2 + 1][1] = r3;
                }
#pragma unroll
                for (int mb = 0; mb < 4; mb++) {
                    if (warpM * 64 + mb * 16 >= cnt) continue;
#pragma unroll
                    for (int nb = 0; nb < 7; nb++)
                        mma16816(acc[mb][nb], loA[nb] ? al[mb] : ah[mb], bq[nb]);
                }
            }
            __syncthreads();
        }

        // ---- epilogue: route by virtual row ----
#pragma unroll
        for (int mb = 0; mb < 4; mb++) {
            int m0 = warpM * 64 + mb * 16 + g;
            int b0 = Slist[m0], b1 = Slist[m0 + 8];
#pragma unroll
            for (int nb = 0; nb < 7; nb++) {
                float* d = acc[mb][nb];
                int vbase = vwarp + nb * 8;
                int n = vbase + tg * 2;
                if (vbase < 768) {
                    float2 bb = *(const float2*)(b_hh + (size_t)ci * Gn + n);
                    if (b0 >= 0) *(float2*)(g_gh + (size_t)b0 * Gn + n) =
                        make_float2(d[0] + bb.x, d[1] + bb.y);
                    if (b1 >= 0) *(float2*)(g_gh + (size_t)b1 * Gn + n) =
                        make_float2(d[2] + bb.x, d[3] + bb.y);
                } else if (vbase < 1024) {
                    int j = n - 768;
                    if (b0 >= 0) *(float2*)(g_pc + (size_t)b0 * Hn + j) = make_float2(d[0], d[1]);
                    if (b1 >= 0) *(float2*)(g_pc + (size_t)b1 * Hn + j) = make_float2(d[2], d[3]);
                } else if (vbase < 1536) {
                    int o = n - 1024;
                    float2 bb = *(const float2*)(bc + (size_t)ci * On + o);
                    if (b0 >= 0) *(float2*)(g_outT + ((size_t)(t - 1) * Bn + b0) * On + o) =
                        make_float2(sigmoidf(d[0] + bb.x), sigmoidf(d[1] + bb.y));
                    if (b1 >= 0) *(float2*)(g_outT + ((size_t)(t - 1) * Bn + b1) * On + o) =
                        make_float2(sigmoidf(d[2] + bb.x), sigmoidf(d[3] + bb.y));
                } else {
                    int j = n - 1536;
                    if (b0 >= 0) *(float2*)(g_pb + (size_t)b0 * Hn + j) = make_float2(d[0], d[1]);
                    if (b1 >= 0) *(float2*)(g_pb + (size_t)b1 * Hn + j) = make_float2(d[2], d[3]);
                }
            }
        }
        CLUSTER_ARRIVE(); CLUSTER_WAIT();    // gh/pb/pc visible; A safe to overwrite
    }
}

// ---------------- final transpose: [T][B][O] -> [B][O][T] ----------------
__global__ void transpose_kernel(float* __restrict__ dout) {
    __shared__ float s[32 * 61];
    int b = blockIdx.y, o0 = blockIdx.x * 32, tid = threadIdx.x;
    for (int idx = tid; idx < 32 * Tn; idx += 256) {
        int t = idx >> 5, oi = idx & 31;
        s[oi * 61 + t] = g_outT[((size_t)t * Bn + b) * On + o0 + oi];
    }
    __syncthreads();
    for (int idx = tid; idx < 32 * Tn; idx += 256) {
        int oi = idx / Tn, t = idx % Tn;
        dout[((size_t)b * On + o0 + oi) * Tn + t] = s[oi * 61 + t];
    }
}

// ---------------- launch ----------------
extern "C" void kernel_launch(void* const* d_in, const int* in_sizes, int n_in,
                              void* d_out, int out_size) {
    const float* x    = (const float*)d_in[0];
    const int*   cam  = (const int*)d_in[1];
    const float* W_ih = (const float*)d_in[2];
    const float* W_hh = (const float*)d_in[3];
    const float* b_ih = (const float*)d_in[4];
    const float* b_hh = (const float*)d_in[5];
    const float* Wc   = (const float*)d_in[6];
    const float* bc   = (const float*)d_in[7];
    float* out = (float*)d_out;

    cudaFuncSetAttribute(gi_kernel, cudaFuncAttributeMaxDynamicSharedMemorySize, SMEM_GI);
    cudaFuncSetAttribute(persist_kernel, cudaFuncAttributeMaxDynamicSharedMemorySize, SMEM_P);

    group_kernel<<<1, Bn>>>(cam);
    prep_w_kernel<<<Cn * 2048, 128>>>(W_hh, Wc, W_ih);
    build_ax_kernel<<<Bn, 128>>>(x, cam);
    init_kernel<<<Bn, 256>>>(cam, b_hh);
    gi_kernel<<<Cn * 6, 128, SMEM_GI>>>(b_ih);           // gi = x@W_ih^T + b_ih

    persist_kernel<<<NCTA, 256, SMEM_P>>>(b_hh, bc);     // clustered 60-step recurrence

    transpose_kernel<<<dim3(On / 32, Bn), 256>>>(out);
}

// round 10
// speedup vs baseline: 1.3907x; 1.3907x over previous
#include <cuda_runtime.h>
#include <cuda_bf16.h>
#include <cstdint>
#include <math.h>

// ---------------- problem constants ----------------
constexpr int Bn = 1024, Hn = 256, Gn = 768, On = 512, Tn = 60, Cn = 15;
constexpr int NCTA = 120;               // 15 clusters x 8 CTAs

// ---------------- device scratch (static, allocation-free) ----------------
__device__ __align__(1024) __nv_bfloat16 g_W [ (size_t)Cn * 1280 * 512 ]; // rows 0-767 W_hh, 768-1279 Wc; [row][hi256|lo256]
__device__ __align__(1024) __nv_bfloat16 g_Wi[ (size_t)Cn * 768 * 512 ];  // W_ih split (one-time gi GEMM)
__device__ __align__(1024) __nv_bfloat16 g_A [ (size_t)Cn * 128 * 512 ];  // A(h): [slot][hi|lo]
__device__ __align__(1024) __nv_bfloat16 g_Ax[ (size_t)Cn * 128 * 512 ];  // A(x)
__device__ float g_gi[Bn * Gn];
__device__ float g_gh[Bn * Gn];          // biases folded; n rows hold full 3-term sum
__device__ float g_h [Bn * Hn];
__device__ float g_outT[(size_t)Tn * Bn * On];   // [T][B][O] staging
__device__ int g_cnt[Cn], g_off[Cn], g_list[Bn], g_slot[Bn];

// ---------------- PTX helpers (family-agnostic) ----------------
__device__ __forceinline__ uint32_t smem_u32(const void* p) {
    uint32_t a;
    asm("{ .reg .u64 t; cvta.to.shared.u64 t, %1; cvt.u32.u64 %0, t; }" : "=r"(a) : "l"(p));
    return a;
}
__device__ __forceinline__ void ldsm4(uint32_t& r0, uint32_t& r1, uint32_t& r2, uint32_t& r3,
                                      uint32_t addr) {
    asm volatile("ldmatrix.sync.aligned.m8n8.x4.shared.b16 {%0,%1,%2,%3}, [%4];"
                 : "=r"(r0), "=r"(r1), "=r"(r2), "=r"(r3) : "r"(addr));
}
__device__ __forceinline__ void mma16816(float* d, const uint32_t* a, const uint32_t* b) {
    asm volatile("mma.sync.aligned.m16n8k16.row.col.f32.bf16.bf16.f32 "
                 "{%0,%1,%2,%3}, {%4,%5,%6,%7}, {%8,%9}, {%0,%1,%2,%3};"
                 : "+f"(d[0]), "+f"(d[1]), "+f"(d[2]), "+f"(d[3])
                 : "r"(a[0]), "r"(a[1]), "r"(a[2]), "r"(a[3]), "r"(b[0]), "r"(b[1]));
}
__device__ __forceinline__ void cp_async16(uint32_t dst, const void* src) {
    asm volatile("cp.async.cg.shared.global [%0], [%1], 16;" :: "r"(dst), "l"(src));
}
#define CP_COMMIT() asm volatile("cp.async.commit_group;" ::: "memory")
#define CP_WAIT1()  asm volatile("cp.async.wait_group 1;" ::: "memory")
#define CP_WAIT0()  asm volatile("cp.async.wait_group 0;" ::: "memory")
#define CLUSTER_ARRIVE() asm volatile("barrier.cluster.arrive.aligned;" ::: "memory")
#define CLUSTER_WAIT()   asm volatile("barrier.cluster.wait.aligned;" ::: "memory")

__device__ __forceinline__ uint32_t swz(uint32_t x) { return x ^ ((x >> 3) & 0x70); }
__device__ __forceinline__ float sigmoidf(float x) { return 1.0f / (1.0f + expf(-x)); }
__device__ __forceinline__ uint32_t pack_bf2(float a, float b) {
    __nv_bfloat162 t = {__float2bfloat16(a), __float2bfloat16(b)};
    return *(uint32_t*)&t;
}

// ---------------- grouping ----------------
__global__ void group_kernel(const int* __restrict__ cam) {
    __shared__ int cnt[Cn], off[Cn], cur[Cn];
    int tid = threadIdx.x;
    if (tid < Cn) { cnt[tid] = 0; cur[tid] = 0; }
    __syncthreads();
    int c = cam[tid];
    atomicAdd(&cnt[c], 1);
    __syncthreads();
    if (tid == 0) { int s = 0; for (int i = 0; i < Cn; i++) { off[i] = s; s += cnt[i]; } }
    __syncthreads();
    if (tid < Cn) { g_cnt[tid] = cnt[tid]; g_off[tid] = off[tid]; }
    int p = atomicAdd(&cur[c], 1);
    g_list[off[c] + p] = tid;
    g_slot[tid] = p;
}

// ---------------- weight hi/lo split ----------------
__global__ void prep_w_kernel(const float* __restrict__ W_hh, const float* __restrict__ Wc,
                              const float* __restrict__ W_ih) {
    int row = blockIdx.x & 2047;
    int c   = blockIdx.x >> 11;
    const float* src;
    __nv_bfloat16* dst;
    if (row < 768) {
        src = W_hh + ((size_t)c * Gn + row) * Hn;
        dst = g_W + ((size_t)c * 1280 + row) * 512;
    } else if (row < 1280) {
        src = Wc + ((size_t)c * On + (row - 768)) * Hn;
        dst = g_W + ((size_t)c * 1280 + row) * 512;
    } else {
        src = W_ih + ((size_t)c * Gn + (row - 1280)) * Hn;
        dst = g_Wi + ((size_t)c * 768 + (row - 1280)) * 512;
    }
    int k0 = threadIdx.x * 2;
    float2 v = *(const float2*)(src + k0);
    float h0 = __bfloat162float(__float2bfloat16(v.x));
    float h1 = __bfloat162float(__float2bfloat16(v.y));
    *(uint32_t*)(dst + k0)       = pack_bf2(v.x, v.y);
    *(uint32_t*)(dst + 256 + k0) = pack_bf2(v.x - h0, v.y - h1);
}

// ---------------- activation hi/lo split ----------------
__device__ __forceinline__ void write_A2(__nv_bfloat16* Abase, int c, int slot,
                                         int k0, float v0, float v1) {
    __nv_bfloat16* row = Abase + ((size_t)c * 128 + slot) * 512;
    float h0 = __bfloat162float(__float2bfloat16(v0));
    float h1 = __bfloat162float(__float2bfloat16(v1));
    *(uint32_t*)(row + k0)       = pack_bf2(v0, v1);
    *(uint32_t*)(row + 256 + k0) = pack_bf2(v0 - h0, v1 - h1);
}

__global__ void build_ax_kernel(const float* __restrict__ x, const int* __restrict__ cam) {
    int b = blockIdx.x, j0 = threadIdx.x * 2;
    float2 v = *(const float2*)(x + (size_t)b * Hn + j0);
    write_A2(g_Ax, cam[b], g_slot[b], j0, v.x, v.y);
}

// h0 = 0; gh0 = b_hh (bias folded into gh)
__global__ void init_kernel(const int* __restrict__ cam, const float* __restrict__ b_hh) {
    int b = blockIdx.x, j = threadIdx.x;
    int c = cam[b];
    g_h[b * Hn + j] = 0.0f;
    g_gh[b * Gn + j]       = b_hh[c * Gn + j];
    g_gh[b * Gn + 256 + j] = b_hh[c * Gn + 256 + j];
    g_gh[b * Gn + 512 + j] = b_hh[c * Gn + 512 + j];
}

// ---------------- gi GEMM (once): gi = x @ W_ih^T + b_ih (full 3-term) ----------------
__device__ __forceinline__ int aoff_f(int cc) { return (((cc >> 2) == 1) ? 256 : 0) + (cc & 3) * 64; }
__device__ __forceinline__ int boff_f(int cc) { return (((cc >> 2) == 2) ? 256 : 0) + (cc & 3) * 64; }

__device__ __forceinline__ void load_tile128(uint32_t sbase, const __nv_bfloat16* src,
                                             int koff, int tid) {
#pragma unroll
    for (int i = 0; i < 8; i++) {
        int idx = i * 128 + tid;
        int row = idx >> 3, c16 = idx & 7;
        cp_async16(sbase + swz((uint32_t)(row * 128 + c16 * 16)),
                   src + (size_t)row * 512 + koff + c16 * 8);
    }
}

constexpr int SMEM_GI = 65536 + 512;

__global__ void __launch_bounds__(128)
gi_kernel(const float* __restrict__ b_ih) {
    extern __shared__ __align__(1024) unsigned char smem[];
    uint32_t sb = smem_u32(smem);
    int tid = threadIdx.x;
    int ci = blockIdx.x / 6, nt = blockIdx.x % 6;
    int* Slist = (int*)(smem + 65536);
    Slist[tid] = (tid < g_cnt[ci]) ? g_list[g_off[ci] + tid] : -1;

    const __nv_bfloat16* Abase = g_Ax + (size_t)ci * 128 * 512;
    const __nv_bfloat16* Wbase = g_Wi + ((size_t)ci * 768 + nt * 128) * 512;

    load_tile128(sb, Abase, aoff_f(0), tid);
    load_tile128(sb + 16384, Wbase, boff_f(0), tid);
    CP_COMMIT();

    int lane = tid & 31, wid = tid >> 5;
    int warpM = wid & 1, warpN = wid >> 1;
    int arow = lane & 15, khalf = (lane >> 4) << 3;

    float acc[4][8][4];
#pragma unroll
    for (int mb = 0; mb < 4; mb++)
#pragma unroll
        for (int nb = 0; nb < 8; nb++)
#pragma unroll
            for (int q = 0; q < 4; q++) acc[mb][nb][q] = 0.0f;

    for (int cc = 0; cc < 12; cc++) {
        int st = cc & 1;
        if (cc < 11) {
            int s1 = st ^ 1;
            load_tile128(sb + s1 * 32768, Abase, aoff_f(cc + 1), tid);
            load_tile128(sb + s1 * 32768 + 16384, Wbase, boff_f(cc + 1), tid);
            CP_COMMIT();
            CP_WAIT1();
        } else CP_WAIT0();
        __syncthreads();
        uint32_t As = sb + st * 32768, Bs = As + 16384;
#pragma unroll
        for (int kc = 0; kc < 4; kc++) {
            int kb = (kc << 4) + khalf;
            uint32_t a[4][4];
#pragma unroll
            for (int mb = 0; mb < 4; mb++)
                ldsm4(a[mb][0], a[mb][1], a[mb][2], a[mb][3],
                      As + swz((uint32_t)((((warpM << 6) + (mb << 4) + arow) << 7) + (kb << 1))));
            uint32_t bq[8][2];
#pragma unroll
            for (int np = 0; np < 4; np++) {
                uint32_t r0, r1, r2, r3;
                ldsm4(r0, r1, r2, r3,
                      Bs + swz((uint32_t)((((warpN << 6) + (np << 4) + arow) << 7) + (kb << 1))));
                bq[np * 2][0] = r0; bq[np * 2 + 1][0] = r1;
                bq[np * 2][1] = r2; bq[np * 2 + 1][1] = r3;
            }
#pragma unroll
            for (int mb = 0; mb < 4; mb++)
#pragma unroll
                for (int nb = 0; nb < 8; nb++)
                    mma16816(acc[mb][nb], a[mb], bq[nb]);
        }
        __syncthreads();
    }

    int g = lane >> 2, tg = lane & 3;
#pragma unroll
    for (int mb = 0; mb < 4; mb++) {
        int m0 = (warpM << 6) + (mb << 4) + g;
        int b0 = Slist[m0], b1 = Slist[m0 + 8];
#pragma unroll
        for (int nb = 0; nb < 8; nb++) {
            float* d = acc[mb][nb];
            int n = nt * 128 + (warpN << 6) + (nb << 3) + (tg << 1);
            float2 bb = *(const float2*)(b_ih + (size_t)ci * Gn + n);
            if (b0 >= 0) *(float2*)(g_gi + (size_t)b0 * Gn + n) = make_float2(d[0] + bb.x, d[1] + bb.y);
            if (b1 >= 0) *(float2*)(g_gi + (size_t)b1 * Gn + n) = make_float2(d[2] + bb.x, d[3] + bb.y);
        }
    }
}

// ---------------- persistent clustered recurrence kernel ----------------
// cluster = 8 CTAs = one camera.
//   rank 0: r rows 0-255   (1-term, K=256)  -> g_gh
//   rank 1: z rows 256-511 (1-term)         -> g_gh
//   rank 2-5: n rows 512+(rank-2)*64, 64 rows, 3-term K'=768 (all in-CTA) -> g_gh
//   rank 6-7: out rows (rank-6)*256, 256 rows, 1-term -> sigmoid -> g_outT
// A is copied fully into SMEM each step; no mid-loop syncs. Out CTAs arrive
// phase-B right after consuming A so their GEMM is off the barrier path.
constexpr uint32_t SBA  = 0;         // A hi: 4 tiles x 16KB = 64KB
constexpr uint32_t SBAL = 65536;     // A lo (n CTAs) OR W base (rz/out CTAs)
constexpr uint32_t SBWN = 131072;    // W base for n CTAs (hi 32KB + lo 32KB)
constexpr uint32_t SBSL = 196608;
constexpr int SMEM_P = 197632;

__global__ void __cluster_dims__(8, 1, 1) __launch_bounds__(256, 1)
persist_kernel(const float* __restrict__ b_hh, const float* __restrict__ bc) {
    extern __shared__ __align__(1024) unsigned char smem[];
    uint32_t sb = smem_u32(smem);
    int tid = threadIdx.x, lane = tid & 31, wid = tid >> 5;
    int ci = blockIdx.x >> 3, rank = blockIdx.x & 7;
    int kind = (rank < 2) ? 0 : (rank < 6 ? 1 : 2);   // 0=rz, 1=n, 2=out
    int* Slist = (int*)(smem + SBSL);
    int cnt = g_cnt[ci];
    if (tid < 128) Slist[tid] = (tid < cnt) ? g_list[g_off[ci] + tid] : -1;

    // ---- prologue: resident weight tile ----
    if (kind == 0 || kind == 2) {      // 256 rows x 256 hi cols -> 4 chunks x 32KB
        int r0 = (kind == 0) ? rank * 256 : 768 + (rank - 6) * 256;
        const __nv_bfloat16* Wb = g_W + ((size_t)ci * 1280 + r0) * 512;
        for (int i = tid; i < 8192; i += 256) {
            int ch = i >> 11, rem = i & 2047;
            int row = rem >> 3, c16 = rem & 7;
            cp_async16(sb + SBAL + ch * 32768 + swz((uint32_t)(row * 128 + c16 * 16)),
                       Wb + (size_t)row * 512 + ch * 64 + c16 * 8);
        }
    } else {                           // 64 rows x (hi 256 | lo 256) -> 2x4 chunks x 8KB
        const __nv_bfloat16* Wb = g_W + ((size_t)ci * 1280 + 512 + (rank - 2) * 64) * 512;
        for (int i = tid; i < 4096; i += 256) {
            int half = i >> 11, j = i & 2047;
            int ch = j >> 9, rem = j & 511;
            int row = rem >> 3, c16 = rem & 7;
            cp_async16(sb + SBWN + half * 32768 + ch * 8192 + swz((uint32_t)(row * 128 + c16 * 16)),
                       Wb + (size_t)row * 512 + half * 256 + ch * 64 + c16 * 8);
        }
    }
    CP_COMMIT(); CP_WAIT0();
    __syncthreads();

    const __nv_bfloat16* Abase = g_A + (size_t)ci * 128 * 512;
    int warpN = wid & 3, warpM = wid >> 2;       // warpN = SMSP id
    int arow = lane & 15, khalf = (lane >> 4) << 3;
    int g = lane >> 2, tg = lane & 3;
    int gslot = rank * 16 + (tid >> 4), gj0 = (tid & 15) * 2;

    for (int t = 1; t <= Tn; t++) {
        // ---- GRU phase (16 slots per CTA) ----
        {
            int b = Slist[gslot];
            if (b >= 0) {
                const float* gi = g_gi + (size_t)b * Gn;
                const float* gh = g_gh + (size_t)b * Gn;
                float* hp = g_h + (size_t)b * Hn;
#pragma unroll
                for (int jj = 0; jj < 8; jj++) {
                    int j = gj0 + jj * 32;
                    float2 gr = __ldcg((const float2*)(gh + j));
                    float2 gz = __ldcg((const float2*)(gh + 256 + j));
                    float2 gn = __ldcg((const float2*)(gh + 512 + j));
                    float2 ir = *(const float2*)(gi + j);
                    float2 iz = *(const float2*)(gi + 256 + j);
                    float2 in_ = *(const float2*)(gi + 512 + j);
                    float2 h = *(const float2*)(hp + j);
                    float r0 = sigmoidf(ir.x + gr.x), r1 = sigmoidf(ir.y + gr.y);
                    float z0 = sigmoidf(iz.x + gz.x), z1 = sigmoidf(iz.y + gz.y);
                    float n0 = tanhf(in_.x + r0 * gn.x), n1 = tanhf(in_.y + r1 * gn.y);
                    float h0 = (1.0f - z0) * n0 + z0 * h.x;
                    float h1 = (1.0f - z1) * n1 + z1 * h.y;
                    *(float2*)(hp + j) = make_float2(h0, h1);
                    write_A2(g_A, ci, gslot, j, h0, h1);
                }
            }
        }
        CLUSTER_ARRIVE(); CLUSTER_WAIT();    // phase A: A(t) ready

        bool doW = (kind == 2) || (t < Tn);  // gh_Tn never consumed
        if (doW) {
            // ---- copy A into SMEM (hi always; lo for n CTAs) ----
            for (int i = tid; i < 4096; i += 256) {
                int ch = i >> 10, rem = i & 1023;
                int row = rem >> 3, c16 = rem & 7;
                cp_async16(sb + SBA + ch * 16384 + swz((uint32_t)(row * 128 + c16 * 16)),
                           Abase + (size_t)row * 512 + ch * 64 + c16 * 8);
            }
            if (kind == 1) {
                for (int i = tid; i < 4096; i += 256) {
                    int ch = i >> 10, rem = i & 1023;
                    int row = rem >> 3, c16 = rem & 7;
                    cp_async16(sb + SBAL + ch * 16384 + swz((uint32_t)(row * 128 + c16 * 16)),
                               Abase + (size_t)row * 512 + 256 + ch * 64 + c16 * 8);
                }
            }
            CP_COMMIT(); CP_WAIT0();
            __syncthreads();
        }

        if (kind == 2) CLUSTER_ARRIVE();     // out: A consumed; GEMM off barrier path

        if (doW) {
            if (kind != 1) {
                // ---- 256 rows x K=256, 1-term ----
                float acc[4][8][4];
#pragma unroll
                for (int mb = 0; mb < 4; mb++)
#pragma unroll
                    for (int nb = 0; nb < 8; nb++)
#pragma unroll
                        for (int q = 0; q < 4; q++) acc[mb][nb][q] = 0.0f;
#pragma unroll 4
                for (int kc = 0; kc < 16; kc++) {
                    int ch = kc >> 2, kb = ((kc & 3) << 4) + khalf;
                    uint32_t af[4][4];
#pragma unroll
                    for (int mb = 0; mb < 4; mb++) {
                        int r0 = (mb * 2 + warpM) * 16;
                        if (r0 < cnt)
                            ldsm4(af[mb][0], af[mb][1], af[mb][2], af[mb][3],
                                  sb + SBA + ch * 16384 +
                                  swz((uint32_t)(((r0 + arow) << 7) + (kb << 1))));
                    }
                    uint32_t bq[8][2];
#pragma unroll
                    for (int np = 0; np < 4; np++) {
                        uint32_t r0, r1, r2, r3;
                        ldsm4(r0, r1, r2, r3,
                              sb + SBAL + ch * 32768 +
                              swz((uint32_t)(((warpN * 64 + np * 16 + arow) << 7) + (kb << 1))));
                        bq[np * 2][0] = r0; bq[np * 2 + 1][0] = r1;
                        bq[np * 2][1] = r2; bq[np * 2 + 1][1] = r3;
                    }
#pragma unroll
                    for (int mb = 0; mb < 4; mb++) {
                        if ((mb * 2 + warpM) * 16 >= cnt) continue;
#pragma unroll
                        for (int nb = 0; nb < 8; nb++)
                            mma16816(acc[mb][nb], af[mb], bq[nb]);
                    }
                }
                // epilogue
#pragma unroll
                for (int mb = 0; mb < 4; mb++) {
                    int m0 = (mb * 2 + warpM) * 16 + g;
                    int b0 = Slist[m0], b1 = Slist[m0 + 8];
#pragma unroll
                    for (int nb = 0; nb < 8; nb++) {
                        float* d = acc[mb][nb];
                        if (kind == 0) {
                            int n = rank * 256 + warpN * 64 + nb * 8 + tg * 2;
                            float2 bb = *(const float2*)(b_hh + (size_t)ci * Gn + n);
                            if (b0 >= 0) *(float2*)(g_gh + (size_t)b0 * Gn + n) =
                                make_float2(d[0] + bb.x, d[1] + bb.y);
                            if (b1 >= 0) *(float2*)(g_gh + (size_t)b1 * Gn + n) =
                                make_float2(d[2] + bb.x, d[3] + bb.y);
                        } else {
                            int o = (rank - 6) * 256 + warpN * 64 + nb * 8 + tg * 2;
                            float2 bb = *(const float2*)(bc + (size_t)ci * On + o);
                            if (b0 >= 0) *(float2*)(g_outT + ((size_t)(t - 1) * Bn + b0) * On + o) =
                                make_float2(sigmoidf(d[0] + bb.x), sigmoidf(d[1] + bb.y));
                            if (b1 >= 0) *(float2*)(g_outT + ((size_t)(t - 1) * Bn + b1) * On + o) =
                                make_float2(sigmoidf(d[2] + bb.x), sigmoidf(d[3] + bb.y));
                        }
                    }
                }
            } else {
                // ---- n gate: 64 rows, 3-term K'=768, all in-CTA ----
                float acc[4][2][4];
#pragma unroll
                for (int mb = 0; mb < 4; mb++)
#pragma unroll
                    for (int nb = 0; nb < 2; nb++)
#pragma unroll
                        for (int q = 0; q < 4; q++) acc[mb][nb][q] = 0.0f;
#pragma unroll
                for (int term = 0; term < 3; term++) {
                    uint32_t aB = (term == 1) ? (sb + SBAL) : (sb + SBA);
                    uint32_t wB = (term == 2) ? (sb + SBWN + 32768) : (sb + SBWN);
#pragma unroll 4
                    for (int kc = 0; kc < 16; kc++) {
                        int ch = kc >> 2, kb = ((kc & 3) << 4) + khalf;
                        uint32_t af[4][4];
#pragma unroll
                        for (int mb = 0; mb < 4; mb++) {
                            int r0 = (mb * 2 + warpM) * 16;
                            if (r0 < cnt)
                                ldsm4(af[mb][0], af[mb][1], af[mb][2], af[mb][3],
                                      aB + ch * 16384 +
                                      swz((uint32_t)(((r0 + arow) << 7) + (kb << 1))));
                        }
                        uint32_t bq[2][2];
                        {
                            uint32_t r0, r1, r2, r3;
                            ldsm4(r0, r1, r2, r3,
                                  wB + ch * 8192 +
                                  swz((uint32_t)(((warpN * 16 + arow) << 7) + (kb << 1))));
                            bq[0][0] = r0; bq[1][0] = r1; bq[0][1] = r2; bq[1][1] = r3;
                        }
#pragma unroll
                        for (int mb = 0; mb < 4; mb++) {
                            if ((mb * 2 + warpM) * 16 >= cnt) continue;
                            mma16816(acc[mb][0], af[mb], bq[0]);
                            mma16816(acc[mb][1], af[mb], bq[1]);
                        }
                    }
                }
#pragma unroll
                for (int mb = 0; mb < 4; mb++) {
                    int m0 = (mb * 2 + warpM) * 16 + g;
                    int b0 = Slist[m0], b1 = Slist[m0 + 8];
#pragma unroll
                    for (int nb = 0; nb < 2; nb++) {
                        float* d = acc[mb][nb];
                        int n = 512 + (rank - 2) * 64 + warpN * 16 + nb * 8 + tg * 2;
                        float2 bb = *(const float2*)(b_hh + (size_t)ci * Gn + n);
                        if (b0 >= 0) *(float2*)(g_gh + (size_t)b0 * Gn + n) =
                            make_float2(d[0] + bb.x, d[1] + bb.y);
                        if (b1 >= 0) *(float2*)(g_gh + (size_t)b1 * Gn + n) =
                            make_float2(d[2] + bb.x, d[3] + bb.y);
                    }
                }
            }
        }

        if (kind != 2) CLUSTER_ARRIVE();     // phase B: gh(t) written
        CLUSTER_WAIT();
    }
}

// ---------------- final transpose: [T][B][O] -> [B][O][T] ----------------
__global__ void transpose_kernel(float* __restrict__ dout) {
    __shared__ float s[32 * 61];
    int b = blockIdx.y, o0 = blockIdx.x * 32, tid = threadIdx.x;
    for (int idx = tid; idx < 32 * Tn; idx += 256) {
        int t = idx >> 5, oi = idx & 31;
        s[oi * 61 + t] = g_outT[((size_t)t * Bn + b) * On + o0 + oi];
    }
    __syncthreads();
    for (int idx = tid; idx < 32 * Tn; idx += 256) {
        int oi = idx / Tn, t = idx % Tn;
        dout[((size_t)b * On + o0 + oi) * Tn + t] = s[oi * 61 + t];
    }
}

// ---------------- launch ----------------
extern "C" void kernel_launch(void* const* d_in, const int* in_sizes, int n_in,
                              void* d_out, int out_size) {
    const float* x    = (const float*)d_in[0];
    const int*   cam  = (const int*)d_in[1];
    const float* W_ih = (const float*)d_in[2];
    const float* W_hh = (const float*)d_in[3];
    const float* b_ih = (const float*)d_in[4];
    const float* b_hh = (const float*)d_in[5];
    const float* Wc   = (const float*)d_in[6];
    const float* bc   = (const float*)d_in[7];
    float* out = (float*)d_out;

    cudaFuncSetAttribute(gi_kernel, cudaFuncAttributeMaxDynamicSharedMemorySize, SMEM_GI);
    cudaFuncSetAttribute(persist_kernel, cudaFuncAttributeMaxDynamicSharedMemorySize, SMEM_P);

    group_kernel<<<1, Bn>>>(cam);
    prep_w_kernel<<<Cn * 2048, 128>>>(W_hh, Wc, W_ih);
    build_ax_kernel<<<Bn, 128>>>(x, cam);
    init_kernel<<<Bn, 256>>>(cam, b_hh);
    gi_kernel<<<Cn * 6, 128, SMEM_GI>>>(b_ih);           // gi = x@W_ih^T + b_ih

    persist_kernel<<<NCTA, 256, SMEM_P>>>(b_hh, bc);     // clustered 60-step recurrence

    transpose_kernel<<<dim3(On / 32, Bn), 256>>>(out);
}